// round 9
// baseline (speedup 1.0000x reference)
#include <cuda_runtime.h>
#include <cstdint>

#define ALPHA_LRELU 0.8f

// f32x2 packed math (Blackwell FFMA2 path — only reachable via PTX).
#define FMA2(d, a, b, c) \
    asm("fma.rn.f32x2 %0, %1, %2, %3;" : "=l"(d) : "l"(a), "l"(b), "l"(c))

__device__ __forceinline__ uint64_t pack2(float lo, float hi) {
    uint64_t r; asm("mov.b64 %0, {%1, %2};" : "=l"(r) : "f"(lo), "f"(hi)); return r;
}
__device__ __forceinline__ float2 unpack2(uint64_t v) {
    float2 r; asm("mov.b64 {%0, %1}, %2;" : "=f"(r.x), "=f"(r.y) : "l"(v)); return r;
}
__device__ __forceinline__ uint64_t d2l(double d) { return __double_as_longlong(d); }

// Scratch (static __device__ arrays are the sanctioned no-alloc workaround).
__device__ __align__(16) float g_agg[50048 * 128];   // attention-aggregated feats

__device__ __forceinline__ float warp_sum(float v) {
    v += __shfl_xor_sync(0xffffffffu, v, 16);
    v += __shfl_xor_sync(0xffffffffu, v, 8);
    v += __shfl_xor_sync(0xffffffffu, v, 4);
    v += __shfl_xor_sync(0xffffffffu, v, 2);
    v += __shfl_xor_sync(0xffffffffu, v, 1);
    return v;
}

// ---------------------------------------------------------------------------
// Kernel A: attention + aggregation. Warp per node, no barriers in the body.
// c1 = W@a_x and c2 = W2@a_n are computed PER BLOCK into smem at startup
// (one length-64 dot per thread, W hot in L2 after the first wave) — this
// removes the former single-block precompute kernel that cost 8.6us of pure
// serial latency in the graph.
// Neighbors processed in PAIRS (two independent shuffle trees in flight).
// __ldcs on the one-touch neigh/edge stream keeps input & g_agg L2-resident.
// Softmax without max-subtraction (|t| <~ 20; validated rel_err 3e-7).
// ---------------------------------------------------------------------------
__global__ __launch_bounds__(256, 4)
void attn_kernel(const float* __restrict__ input,
                 const float* __restrict__ neigh,
                 const float* __restrict__ edge,
                 const float* __restrict__ W,
                 const float* __restrict__ W2,
                 const float* __restrict__ a,
                 float* __restrict__ out, int N) {
    __shared__ __align__(16) float c1_s[128];
    __shared__ __align__(16) float c2_s[128];

    // --- per-block c1/c2: thread t handles k = t>>1 of (t&1 ? W2 : W) ---
    {
        const int t = threadIdx.x;
        const int k = t >> 1;
        const int which = t & 1;
        const float* Wp = which ? (W2 + k * 64) : (W + k * 64);
        const float* ap = which ? (a + 64) : a;
        float s = 0.f;
#pragma unroll
        for (int i = 0; i < 16; ++i) {
            const float4 wv = ((const float4*)Wp)[i];
            const float4 av = ((const float4*)ap)[i];
            s += wv.x * av.x + wv.y * av.y + wv.z * av.z + wv.w * av.w;
        }
        if (which) c2_s[k] = s; else c1_s[k] = s;
    }
    __syncthreads();

    const int w = threadIdx.x >> 5;
    const int l = threadIdx.x & 31;
    const int n = blockIdx.x * 8 + w;
    if (n >= N) return;

    const float4 c1v = ((const float4*)c1_s)[l];
    const float4 c2v = ((const float4*)c2_s)[l];
    const float  aev = a[128 + l];

    const float4 in4 = ((const float4*)(input + (long long)n * 128))[l];
    const float sx = warp_sum(in4.x * c1v.x + in4.y * c1v.y +
                              in4.z * c1v.z + in4.w * c1v.w);

    const float4* nrow = (const float4*)(neigh + (long long)n * 2048);
    const float*  erow = edge + (long long)n * 512;

    float sum = 0.f, agge = 0.f;
    float4 agg = make_float4(0.f, 0.f, 0.f, 0.f);
#pragma unroll
    for (int s = 0; s < 16; s += 2) {
        const float4 va = __ldcs(&nrow[s * 32 + l]);
        const float4 vb = __ldcs(&nrow[(s + 1) * 32 + l]);
        const float  ea = __ldcs(&erow[s * 32 + l]);
        const float  eb = __ldcs(&erow[(s + 1) * 32 + l]);
        // Two independent reduction trees — interleaved by the scheduler.
        float qa = va.x * c2v.x + va.y * c2v.y + va.z * c2v.z + va.w * c2v.w
                 + ea * aev;
        float qb = vb.x * c2v.x + vb.y * c2v.y + vb.z * c2v.z + vb.w * c2v.w
                 + eb * aev;
        qa += __shfl_xor_sync(0xffffffffu, qa, 16);
        qb += __shfl_xor_sync(0xffffffffu, qb, 16);
        qa += __shfl_xor_sync(0xffffffffu, qa, 8);
        qb += __shfl_xor_sync(0xffffffffu, qb, 8);
        qa += __shfl_xor_sync(0xffffffffu, qa, 4);
        qb += __shfl_xor_sync(0xffffffffu, qb, 4);
        qa += __shfl_xor_sync(0xffffffffu, qa, 2);
        qb += __shfl_xor_sync(0xffffffffu, qb, 2);
        qa += __shfl_xor_sync(0xffffffffu, qa, 1);
        qb += __shfl_xor_sync(0xffffffffu, qb, 1);
        float ta = sx + qa;
        float tb = sx + qb;
        ta = (ta > 0.f) ? ta : ALPHA_LRELU * ta;
        tb = (tb > 0.f) ? tb : ALPHA_LRELU * tb;
        const float pa = __expf(ta);
        const float pb = __expf(tb);
        sum  += pa + pb;
        agg.x += pa * va.x + pb * vb.x;
        agg.y += pa * va.y + pb * vb.y;
        agg.z += pa * va.z + pb * vb.z;
        agg.w += pa * va.w + pb * vb.w;
        agge  += pa * ea + pb * eb;
    }
    const float inv = 1.f / sum;
    agg.x *= inv; agg.y *= inv; agg.z *= inv; agg.w *= inv;
    ((float4*)(g_agg + (long long)n * 128))[l] = agg;   // default policy: stays in L2
    out[(long long)n * 160 + 128 + l] = agge * inv;     // h_edge
}

// ---------------------------------------------------------------------------
// Kernel B: out[:,0:64] = input @ W ; out[:,64:128] = g_agg @ W2.
// Reg-resident weights (1 col x half-k per thread), smem-staged node rows,
// FFMA2 math, shfl_xor(16) half-combine. Inputs are L2 hits after kernel A.
// ---------------------------------------------------------------------------
#define B_TILE 16
__global__ __launch_bounds__(256, 2)
void gemm_kernel(const float* __restrict__ input,
                 const float* __restrict__ W,
                 const float* __restrict__ W2,
                 float* __restrict__ out, int N) {
    __shared__ __align__(16) float in_s[B_TILE * 128];
    __shared__ __align__(16) float ag_s[B_TILE * 128];

    const int tid  = threadIdx.x;
    const int w    = tid >> 5;
    const int lane = tid & 31;
    const int cl   = lane & 15;     // col within warp
    const int h    = lane >> 4;     // k-half parity (interleaved float4s)
    const int col  = w * 16 + cl;   // 0..127
    const int c    = col & 63;
    const float* Wsrc = (col < 64) ? W : W2;

    // Weight prefetch into registers: k-dims { 8i + 4h + 0..3 }, i = 0..15.
    uint64_t wreg[32];
#pragma unroll
    for (int i = 0; i < 16; ++i) {
        const int k = 8 * i + 4 * h;
        const float s0 = Wsrc[(k + 0) * 64 + c];
        const float s1 = Wsrc[(k + 1) * 64 + c];
        const float s2 = Wsrc[(k + 2) * 64 + c];
        const float s3 = Wsrc[(k + 3) * 64 + c];
        wreg[2 * i]     = pack2(s0, s1);
        wreg[2 * i + 1] = pack2(s2, s3);
    }
    const float* srcbase = (col < 64) ? in_s : ag_s;

    for (int t0 = blockIdx.x * B_TILE; t0 < N; t0 += gridDim.x * B_TILE) {
        __syncthreads();   // previous tile fully consumed
        for (int i = tid; i < B_TILE * 32; i += 256) {
            const int node = i >> 5;
            const int q    = i & 31;
            const int nn   = t0 + node;
            if (nn < N) {
                ((float4*)in_s)[i] = ((const float4*)(input + (long long)nn * 128))[q];
                ((float4*)ag_s)[i] = ((const float4*)(g_agg + (long long)nn * 128))[q];
            }
        }
        __syncthreads();

        const int jmax = (N - t0 < B_TILE) ? (N - t0) : B_TILE;
        for (int j = 0; j < jmax; ++j) {
            const double2* row = (const double2*)(srcbase + j * 128);
            uint64_t acc = 0ull;   // packed (0.f, 0.f)
#pragma unroll
            for (int i = 0; i < 16; ++i) {
                const double2 v = row[2 * i + h];   // dims 8i+4h .. +3
                FMA2(acc, wreg[2 * i],     d2l(v.x), acc);
                FMA2(acc, wreg[2 * i + 1], d2l(v.y), acc);
            }
            const float2 u = unpack2(acc);
            float r = u.x + u.y;
            r += __shfl_xor_sync(0xffffffffu, r, 16);   // combine k-halves
            if (h == 0) out[(long long)(t0 + j) * 160 + col] = r;
        }
    }
}

extern "C" void kernel_launch(void* const* d_in, const int* in_sizes, int n_in,
                              void* d_out, int out_size) {
    const float* input = (const float*)d_in[0];
    const float* neigh = (const float*)d_in[1];
    const float* edge  = (const float*)d_in[2];
    const float* W     = (const float*)d_in[3];
    const float* W2    = (const float*)d_in[4];
    const float* a     = (const float*)d_in[5];
    float* out = (float*)d_out;

    const int N = in_sizes[0] / 128;

    attn_kernel<<<(N + 7) / 8, 256>>>(input, neigh, edge, W, W2, a, out, N);
    gemm_kernel<<<592, 256>>>(input, W, W2, out, N);
}

// round 11
// speedup vs baseline: 1.0990x; 1.0990x over previous
#include <cuda_runtime.h>
#include <cstdint>

#define ALPHA_LRELU 0.8f

// f32x2 packed math (Blackwell FFMA2 path — only reachable via PTX).
#define FMA2(d, a, b, c) \
    asm("fma.rn.f32x2 %0, %1, %2, %3;" : "=l"(d) : "l"(a), "l"(b), "l"(c))

__device__ __forceinline__ uint64_t pack2(float lo, float hi) {
    uint64_t r; asm("mov.b64 %0, {%1, %2};" : "=l"(r) : "f"(lo), "f"(hi)); return r;
}
__device__ __forceinline__ float2 unpack2(uint64_t v) {
    float2 r; asm("mov.b64 {%0, %1}, %2;" : "=f"(r.x), "=f"(r.y) : "l"(v)); return r;
}
__device__ __forceinline__ uint64_t d2l(double d) { return __double_as_longlong(d); }

// Scratch (static __device__ arrays are the sanctioned no-alloc workaround).
__device__ __align__(16) float g_c1[128];            // W  @ a_x
__device__ __align__(16) float g_c2[128];            // W2 @ a_n
__device__ __align__(16) float g_agg[50048 * 128];   // attention-aggregated feats

// Low-latency precompute: 1024 threads; 4 lanes cooperate per output k
// (4 independent float4 loads deep, 2-level shfl reduce).
__global__ void precompute_kernel(const float* __restrict__ W,
                                  const float* __restrict__ W2,
                                  const float* __restrict__ a) {
    const int t    = threadIdx.x;
    const int warp = t >> 5;
    const int lane = t & 31;
    const int which = warp >> 4;                 // 0: c1/W, 1: c2/W2
    const int k     = (warp & 15) * 8 + (lane >> 2);
    const int part  = lane & 3;                  // 16 floats each
    const float* Wp = which ? W2 : W;
    const float* ap = which ? (a + 64) : a;
    const float4* row = (const float4*)(Wp + k * 64) + part * 4;
    const float4* av  = (const float4*)ap + part * 4;
    float s = 0.f;
#pragma unroll
    for (int i = 0; i < 4; ++i) {
        const float4 wv = row[i];
        const float4 x  = av[i];
        s += wv.x * x.x + wv.y * x.y + wv.z * x.z + wv.w * x.w;
    }
    s += __shfl_xor_sync(0xffffffffu, s, 1);
    s += __shfl_xor_sync(0xffffffffu, s, 2);
    if (part == 0) { if (which) g_c2[k] = s; else g_c1[k] = s; }
}

__device__ __forceinline__ float warp_sum(float v) {
    v += __shfl_xor_sync(0xffffffffu, v, 16);
    v += __shfl_xor_sync(0xffffffffu, v, 8);
    v += __shfl_xor_sync(0xffffffffu, v, 4);
    v += __shfl_xor_sync(0xffffffffu, v, 2);
    v += __shfl_xor_sync(0xffffffffu, v, 1);
    return v;
}

// ---------------------------------------------------------------------------
// Kernel A (R8-proven, at DRAM roofline): attention + aggregation.
// Warp per node, no smem/barriers; neighbor pairs (two shuffle trees in
// flight); __ldcs on one-touch neigh/edge keeps input & g_agg L2-resident.
// Softmax without max-subtraction (|t| <~ 20; validated rel_err 3e-7).
// ---------------------------------------------------------------------------
__global__ __launch_bounds__(256, 4)
void attn_kernel(const float* __restrict__ input,
                 const float* __restrict__ neigh,
                 const float* __restrict__ edge,
                 const float* __restrict__ a,
                 float* __restrict__ out, int N) {
    const int w = threadIdx.x >> 5;
    const int l = threadIdx.x & 31;
    const int n = blockIdx.x * 8 + w;
    if (n >= N) return;

    const float4 c2v = ((const float4*)g_c2)[l];
    const float  aev = a[128 + l];

    const float4 in4 = ((const float4*)(input + (long long)n * 128))[l];
    const float4 c1v = ((const float4*)g_c1)[l];
    const float sx = warp_sum(in4.x * c1v.x + in4.y * c1v.y +
                              in4.z * c1v.z + in4.w * c1v.w);

    const float4* nrow = (const float4*)(neigh + (long long)n * 2048);
    const float*  erow = edge + (long long)n * 512;

    float sum = 0.f, agge = 0.f;
    float4 agg = make_float4(0.f, 0.f, 0.f, 0.f);
#pragma unroll
    for (int s = 0; s < 16; s += 2) {
        const float4 va = __ldcs(&nrow[s * 32 + l]);
        const float4 vb = __ldcs(&nrow[(s + 1) * 32 + l]);
        const float  ea = __ldcs(&erow[s * 32 + l]);
        const float  eb = __ldcs(&erow[(s + 1) * 32 + l]);
        float qa = va.x * c2v.x + va.y * c2v.y + va.z * c2v.z + va.w * c2v.w
                 + ea * aev;
        float qb = vb.x * c2v.x + vb.y * c2v.y + vb.z * c2v.z + vb.w * c2v.w
                 + eb * aev;
        qa += __shfl_xor_sync(0xffffffffu, qa, 16);
        qb += __shfl_xor_sync(0xffffffffu, qb, 16);
        qa += __shfl_xor_sync(0xffffffffu, qa, 8);
        qb += __shfl_xor_sync(0xffffffffu, qb, 8);
        qa += __shfl_xor_sync(0xffffffffu, qa, 4);
        qb += __shfl_xor_sync(0xffffffffu, qb, 4);
        qa += __shfl_xor_sync(0xffffffffu, qa, 2);
        qb += __shfl_xor_sync(0xffffffffu, qb, 2);
        qa += __shfl_xor_sync(0xffffffffu, qa, 1);
        qb += __shfl_xor_sync(0xffffffffu, qb, 1);
        float ta = sx + qa;
        float tb = sx + qb;
        ta = (ta > 0.f) ? ta : ALPHA_LRELU * ta;
        tb = (tb > 0.f) ? tb : ALPHA_LRELU * tb;
        const float pa = __expf(ta);
        const float pb = __expf(tb);
        sum  += pa + pb;
        agg.x += pa * va.x + pb * vb.x;
        agg.y += pa * va.y + pb * vb.y;
        agg.z += pa * va.z + pb * vb.z;
        agg.w += pa * va.w + pb * vb.w;
        agge  += pa * ea + pb * eb;
    }
    const float inv = 1.f / sum;
    agg.x *= inv; agg.y *= inv; agg.z *= inv; agg.w *= inv;
    ((float4*)(g_agg + (long long)n * 128))[l] = agg;
    out[(long long)n * 160 + 128 + l] = agge * inv;   // h_edge
}

// ---------------------------------------------------------------------------
// Kernel B v2: blockIdx.y=0 -> out[:,0:64] = input@W ; y=1 -> out[:,64:128]
// = g_agg@W2.  4 lanes cooperate per output column (quarter-k each):
// wreg = 32 regs -> ~60 regs total -> 4 CTAs/SM (2x R9 occupancy).
// Per j: 8 LDS.128 + 16 FFMA2 (64-cyc chain) + 2 shfl. Persistent blocks
// so weights load once per block (19MB, not 200MB, of L2 traffic).
// ---------------------------------------------------------------------------
#define B_TILE 16
__global__ __launch_bounds__(256, 4)
void gemm_kernel(const float* __restrict__ input,
                 const float* __restrict__ W,
                 const float* __restrict__ W2,
                 float* __restrict__ out, int N) {
    __shared__ __align__(16) float src_s[B_TILE * 128];   // 8KB

    const int tid  = threadIdx.x;
    const int warp = tid >> 5;
    const int lane = tid & 31;
    const int c8   = lane & 7;          // col within warp
    const int q    = lane >> 3;         // k-quarter (0..3)
    const int half = blockIdx.y;        // 0: W/input, 1: W2/g_agg
    const float* Wsrc = half ? W2 : W;
    const float* gsrc = half ? (const float*)g_agg : input;
    const int col_local = warp * 8 + c8;        // 0..63
    const int outcol    = half * 64 + col_local;

    // Weight prefetch: k = q*32 + kk, kk = 0..31, packed in pairs.
    uint64_t wreg[16];
#pragma unroll
    for (int kk = 0; kk < 32; kk += 2) {
        const float w0 = Wsrc[(q * 32 + kk)     * 64 + col_local];
        const float w1 = Wsrc[(q * 32 + kk + 1) * 64 + col_local];
        wreg[kk >> 1] = pack2(w0, w1);
    }

    for (int t0 = blockIdx.x * B_TILE; t0 < N; t0 += gridDim.x * B_TILE) {
        __syncthreads();   // previous tile fully consumed
        for (int i = tid; i < B_TILE * 32; i += 256) {
            const int nn = t0 + (i >> 5);
            if (nn < N)
                ((float4*)src_s)[i] =
                    ((const float4*)(gsrc + (long long)nn * 128))[i & 31];
        }
        __syncthreads();

        const int jmax = (N - t0 < B_TILE) ? (N - t0) : B_TILE;
        for (int j = 0; j < jmax; ++j) {
            const double2* row = (const double2*)(src_s + j * 128 + q * 32);
            uint64_t acc = 0ull;   // packed (0.f, 0.f)
#pragma unroll
            for (int i = 0; i < 8; ++i) {
                const double2 v = row[i];
                FMA2(acc, wreg[2 * i],     d2l(v.x), acc);
                FMA2(acc, wreg[2 * i + 1], d2l(v.y), acc);
            }
            const float2 u = unpack2(acc);
            float r = u.x + u.y;
            r += __shfl_xor_sync(0xffffffffu, r, 8);    // combine quarters
            r += __shfl_xor_sync(0xffffffffu, r, 16);
            if (q == 0) out[(long long)(t0 + j) * 160 + outcol] = r;
        }
    }
}

extern "C" void kernel_launch(void* const* d_in, const int* in_sizes, int n_in,
                              void* d_out, int out_size) {
    const float* input = (const float*)d_in[0];
    const float* neigh = (const float*)d_in[1];
    const float* edge  = (const float*)d_in[2];
    const float* W     = (const float*)d_in[3];
    const float* W2    = (const float*)d_in[4];
    const float* a     = (const float*)d_in[5];
    float* out = (float*)d_out;

    const int N = in_sizes[0] / 128;

    precompute_kernel<<<1, 1024>>>(W, W2, a);
    attn_kernel<<<(N + 7) / 8, 256>>>(input, neigh, edge, a, out, N);
    gemm_kernel<<<dim3(296, 2), 256>>>(input, W, W2, out, N);
}

// round 13
// speedup vs baseline: 1.4783x; 1.3452x over previous
#include <cuda_runtime.h>
#include <cstdint>

#define ALPHA_LRELU 0.8f

// f32x2 packed math (Blackwell FFMA2 path — only reachable via PTX).
#define FMA2(d, a, b, c) \
    asm("fma.rn.f32x2 %0, %1, %2, %3;" : "=l"(d) : "l"(a), "l"(b), "l"(c))

__device__ __forceinline__ float2 unpack2(uint64_t v) {
    float2 r; asm("mov.b64 {%0, %1}, %2;" : "=f"(r.x), "=f"(r.y) : "l"(v)); return r;
}
__device__ __forceinline__ uint64_t d2l(double d) { return __double_as_longlong(d); }

// Scratch (static __device__ arrays are the sanctioned no-alloc workaround).
__device__ __align__(16) float g_c1[128];            // W  @ a_x
__device__ __align__(16) float g_c2[128];            // W2 @ a_n
__device__ __align__(16) float g_agg[50048 * 128];   // attention-aggregated feats

// Low-latency precompute: 1024 threads; 4 lanes cooperate per output k.
__global__ void precompute_kernel(const float* __restrict__ W,
                                  const float* __restrict__ W2,
                                  const float* __restrict__ a) {
    const int t    = threadIdx.x;
    const int warp = t >> 5;
    const int lane = t & 31;
    const int which = warp >> 4;                 // 0: c1/W, 1: c2/W2
    const int k     = (warp & 15) * 8 + (lane >> 2);
    const int part  = lane & 3;
    const float* Wp = which ? W2 : W;
    const float* ap = which ? (a + 64) : a;
    const float4* row = (const float4*)(Wp + k * 64) + part * 4;
    const float4* av  = (const float4*)ap + part * 4;
    float s = 0.f;
#pragma unroll
    for (int i = 0; i < 4; ++i) {
        const float4 wv = row[i];
        const float4 x  = av[i];
        s += wv.x * x.x + wv.y * x.y + wv.z * x.z + wv.w * x.w;
    }
    s += __shfl_xor_sync(0xffffffffu, s, 1);
    s += __shfl_xor_sync(0xffffffffu, s, 2);
    if (part == 0) { if (which) g_c2[k] = s; else g_c1[k] = s; }
}

__device__ __forceinline__ float warp_sum(float v) {
    v += __shfl_xor_sync(0xffffffffu, v, 16);
    v += __shfl_xor_sync(0xffffffffu, v, 8);
    v += __shfl_xor_sync(0xffffffffu, v, 4);
    v += __shfl_xor_sync(0xffffffffu, v, 2);
    v += __shfl_xor_sync(0xffffffffu, v, 1);
    return v;
}

// ---------------------------------------------------------------------------
// Kernel A (R8-proven, at DRAM roofline ~73us): attention + aggregation.
// ---------------------------------------------------------------------------
__global__ __launch_bounds__(256, 4)
void attn_kernel(const float* __restrict__ input,
                 const float* __restrict__ neigh,
                 const float* __restrict__ edge,
                 const float* __restrict__ a,
                 float* __restrict__ out, int N) {
    const int w = threadIdx.x >> 5;
    const int l = threadIdx.x & 31;
    const int n = blockIdx.x * 8 + w;
    if (n >= N) return;

    const float4 c2v = ((const float4*)g_c2)[l];
    const float  aev = a[128 + l];

    const float4 in4 = ((const float4*)(input + (long long)n * 128))[l];
    const float4 c1v = ((const float4*)g_c1)[l];
    const float sx = warp_sum(in4.x * c1v.x + in4.y * c1v.y +
                              in4.z * c1v.z + in4.w * c1v.w);

    const float4* nrow = (const float4*)(neigh + (long long)n * 2048);
    const float*  erow = edge + (long long)n * 512;

    float sum = 0.f, agge = 0.f;
    float4 agg = make_float4(0.f, 0.f, 0.f, 0.f);
#pragma unroll
    for (int s = 0; s < 16; s += 2) {
        const float4 va = __ldcs(&nrow[s * 32 + l]);
        const float4 vb = __ldcs(&nrow[(s + 1) * 32 + l]);
        const float  ea = __ldcs(&erow[s * 32 + l]);
        const float  eb = __ldcs(&erow[(s + 1) * 32 + l]);
        float qa = va.x * c2v.x + va.y * c2v.y + va.z * c2v.z + va.w * c2v.w
                 + ea * aev;
        float qb = vb.x * c2v.x + vb.y * c2v.y + vb.z * c2v.z + vb.w * c2v.w
                 + eb * aev;
        qa += __shfl_xor_sync(0xffffffffu, qa, 16);
        qb += __shfl_xor_sync(0xffffffffu, qb, 16);
        qa += __shfl_xor_sync(0xffffffffu, qa, 8);
        qb += __shfl_xor_sync(0xffffffffu, qb, 8);
        qa += __shfl_xor_sync(0xffffffffu, qa, 4);
        qb += __shfl_xor_sync(0xffffffffu, qb, 4);
        qa += __shfl_xor_sync(0xffffffffu, qa, 2);
        qb += __shfl_xor_sync(0xffffffffu, qb, 2);
        qa += __shfl_xor_sync(0xffffffffu, qa, 1);
        qb += __shfl_xor_sync(0xffffffffu, qb, 1);
        float ta = sx + qa;
        float tb = sx + qb;
        ta = (ta > 0.f) ? ta : ALPHA_LRELU * ta;
        tb = (tb > 0.f) ? tb : ALPHA_LRELU * tb;
        const float pa = __expf(ta);
        const float pb = __expf(tb);
        sum  += pa + pb;
        agg.x += pa * va.x + pb * vb.x;
        agg.y += pa * va.y + pb * vb.y;
        agg.z += pa * va.z + pb * vb.z;
        agg.w += pa * va.w + pb * vb.w;
        agge  += pa * ea + pb * eb;
    }
    const float inv = 1.f / sum;
    agg.x *= inv; agg.y *= inv; agg.z *= inv; agg.w *= inv;
    ((float4*)(g_agg + (long long)n * 128))[l] = agg;
    out[(long long)n * 160 + 128 + l] = agge * inv;   // h_edge
}

// ---------------------------------------------------------------------------
// Kernel B v3: register-tiled GEMM. Block tile: 32 nodes x 128 cols.
// Thread tile: 4 nodes x 4 cols (warp: 32 nodes x 16 cols; warps 0-3 do
// input@W, 4-7 do g_agg@W2). Per k-quad: 8 LDS.128 + 32 FFMA2 (8:1 FMA:LDS).
// Both smem tiles rotation-swizzled (rot = (k4 + idx>>2) & 31): lane-step-1
// rotations -> 8 adjacent 16B regions -> conflict-free LDS.128.
// FFMA2 packed over k-parity: packed operands come straight from LDS as
// double2, zero pack instructions. Epilogue: one STG.128 per node.
// ---------------------------------------------------------------------------
#define B_TILE 32
__global__ __launch_bounds__(256, 2)
void gemm_kernel(const float* __restrict__ input,
                 const float* __restrict__ W,
                 const float* __restrict__ W2,
                 float* __restrict__ out, int N) {
    extern __shared__ float sh[];
    float* in_s = sh;              // 32 x 128 (swizzled)         16KB
    float* ag_s = sh + 4096;       // 32 x 128 (swizzled)         16KB
    float* wt_s = sh + 8192;       // 2 x [64 cols x 128 k] swiz  64KB

    const int tid = threadIdx.x;

    // ---- Stage W^T (swizzled), once per persistent block ----
    for (int i = tid; i < 4096; i += 256) {
        const int which = i >> 11;
        const int i2 = i & 2047;
        const int k  = i2 >> 4;           // 0..127
        const int c0 = (i2 & 15) * 4;     // 0..60
        const float4 v = ((const float4*)((which ? W2 : W) + k * 64))[i2 & 15];
        float* dst = wt_s + which * 8192;
        const int k4 = k >> 2, kr = k & 3;
        dst[(c0 + 0) * 128 + (((k4 + ((c0 + 0) >> 2)) & 31) << 2) + kr] = v.x;
        dst[(c0 + 1) * 128 + (((k4 + ((c0 + 1) >> 2)) & 31) << 2) + kr] = v.y;
        dst[(c0 + 2) * 128 + (((k4 + ((c0 + 2) >> 2)) & 31) << 2) + kr] = v.z;
        dst[(c0 + 3) * 128 + (((k4 + ((c0 + 3) >> 2)) & 31) << 2) + kr] = v.w;
    }

    const int lane = tid & 31;
    const int wrp  = tid >> 5;
    const int half = wrp >> 2;          // 0: input@W, 1: g_agg@W2
    const int ng   = lane >> 2;         // node group (0..7)
    const int cg   = lane & 3;          // col group (0..3)
    const int c0   = (wrp & 3) * 16 + cg * 4;
    const float* srcb = half ? ag_s : in_s;
    const float* wb   = wt_s + half * 8192;

    for (int t0 = blockIdx.x * B_TILE; t0 < N; t0 += gridDim.x * B_TILE) {
        __syncthreads();   // previous tile consumed (also orders W staging)
        // ---- Stage 32 nodes of input and g_agg (swizzled) ----
        for (int i = tid; i < 2048; i += 256) {
            const int which = i >> 10;
            const int r  = (i >> 5) & 31;
            const int k4 = i & 31;
            const int n  = t0 + r;
            if (n < N) {
                const float* g = which ? (g_agg + (long long)n * 128)
                                       : (input + (long long)n * 128);
                float* dst = which ? ag_s : in_s;
                *(float4*)(dst + r * 128 + (((k4 + (r >> 2)) & 31) << 2)) =
                    ((const float4*)g)[k4];
            }
        }
        __syncthreads();

        uint64_t acc[4][4];
#pragma unroll
        for (int i = 0; i < 4; ++i)
#pragma unroll
            for (int j = 0; j < 4; ++j) acc[i][j] = 0ull;

#pragma unroll 4
        for (int k4 = 0; k4 < 32; ++k4) {
            uint64_t s0[4], s1[4], w0[4], w1[4];
            const int srot = ((k4 + ng) & 31) << 2;
#pragma unroll
            for (int i = 0; i < 4; ++i) {
                const double2 v =
                    *(const double2*)(srcb + (4 * ng + i) * 128 + srot);
                s0[i] = d2l(v.x); s1[i] = d2l(v.y);
            }
#pragma unroll
            for (int j = 0; j < 4; ++j) {
                const int c = c0 + j;
                const double2 v =
                    *(const double2*)(wb + c * 128 + (((k4 + (c >> 2)) & 31) << 2));
                w0[j] = d2l(v.x); w1[j] = d2l(v.y);
            }
#pragma unroll
            for (int i = 0; i < 4; ++i)
#pragma unroll
                for (int j = 0; j < 4; ++j) {
                    FMA2(acc[i][j], s0[i], w0[j], acc[i][j]);
                    FMA2(acc[i][j], s1[i], w1[j], acc[i][j]);
                }
        }

        // ---- Epilogue: one STG.128 per node ----
#pragma unroll
        for (int i = 0; i < 4; ++i) {
            const int n = t0 + 4 * ng + i;
            if (n < N) {
                float4 r; float2 u;
                u = unpack2(acc[i][0]); r.x = u.x + u.y;
                u = unpack2(acc[i][1]); r.y = u.x + u.y;
                u = unpack2(acc[i][2]); r.z = u.x + u.y;
                u = unpack2(acc[i][3]); r.w = u.x + u.y;
                *(float4*)(out + (long long)n * 160 + half * 64 + c0) = r;
            }
        }
    }
}

extern "C" void kernel_launch(void* const* d_in, const int* in_sizes, int n_in,
                              void* d_out, int out_size) {
    const float* input = (const float*)d_in[0];
    const float* neigh = (const float*)d_in[1];
    const float* edge  = (const float*)d_in[2];
    const float* W     = (const float*)d_in[3];
    const float* W2    = (const float*)d_in[4];
    const float* a     = (const float*)d_in[5];
    float* out = (float*)d_out;

    const int N = in_sizes[0] / 128;

    const int gemm_smem = (4096 + 4096 + 16384) * 4;   // 96KB
    cudaFuncSetAttribute(gemm_kernel,
                         cudaFuncAttributeMaxDynamicSharedMemorySize, gemm_smem);

    precompute_kernel<<<1, 1024>>>(W, W2, a);
    attn_kernel<<<(N + 7) / 8, 256>>>(input, neigh, edge, a, out, N);
    gemm_kernel<<<296, 256, gemm_smem>>>(input, W, W2, out, N);
}